// round 6
// baseline (speedup 1.0000x reference)
#include <cuda_runtime.h>
#include <cstdint>

// Shapes (fixed by the problem)
#define BB   4
#define TT   512
#define FF   93
#define DSS  64
#define DD   1024
#define HH   8
#define MM   (BB*TT)      // 2048 rows

// Scratch (static device allocations; no cudaMalloc allowed)
__device__ float    g_y0pre[MM*DSS];      // spectral fct output pre-Wos  [2048,64]
__device__ float    g_WosWt[DSS*DD];      // Wos @ Wt                     [64,1024]
__device__ uint32_t g_xt32[MM*DD];        // temporal input, tf32 bits, k-permuted
__device__ uint32_t g_wT32[4*DD*DD];      // Wq,Wk,Wv,Wo transposed [n][k'], tf32 bits
__device__ float    g_qkv[3*MM*DD];       // Q,K,V (float)
__device__ uint32_t g_attnout32[MM*DD];   // attention out, tf32 bits, k-permuted

// ---------------------------------------------------------------------------
// helpers
// ---------------------------------------------------------------------------
__device__ __forceinline__ uint32_t f2tf32(float x) {
    uint32_t r;
    asm("cvt.rna.tf32.f32 %0, %1;" : "=r"(r) : "f"(x));
    return r;
}
// k-permutation within each 8-group: pairs (t, t+4) become adjacent (2t, 2t+1)
__device__ __forceinline__ int kperm(int k) {
    return (k & ~7) | ((k & 3) << 1) | ((k >> 2) & 1);
}
__device__ __forceinline__ void mma_tf32(float c[4], const uint32_t a[4], const uint32_t b[2]) {
    asm volatile(
        "mma.sync.aligned.m16n8k8.row.col.f32.tf32.tf32.f32 "
        "{%0,%1,%2,%3}, {%4,%5,%6,%7}, {%8,%9}, {%0,%1,%2,%3};"
        : "+f"(c[0]), "+f"(c[1]), "+f"(c[2]), "+f"(c[3])
        : "r"(a[0]), "r"(a[1]), "r"(a[2]), "r"(a[3]), "r"(b[0]), "r"(b[1]));
}

// ---------------------------------------------------------------------------
// prep: W[k][n] -> WT[n][perm(k)] as tf32 bits (tiled transpose).
// grid (32, 32, 4), block (32, 8)
// ---------------------------------------------------------------------------
__global__ void prep_weights_kernel(const float* __restrict__ Wq,
                                    const float* __restrict__ Wk,
                                    const float* __restrict__ Wv,
                                    const float* __restrict__ Wo) {
    __shared__ float tile[32][33];
    const int z = blockIdx.z;
    const float* S = (z == 0) ? Wq : (z == 1) ? Wk : (z == 2) ? Wv : Wo;
    uint32_t* D = g_wT32 + (size_t)z * DD * DD;

    const int tx = threadIdx.x, ty = threadIdx.y;
    const int n0 = blockIdx.x * 32, k0 = blockIdx.y * 32;

    #pragma unroll
    for (int j = 0; j < 4; j++)
        tile[ty + 8*j][tx] = S[(size_t)(k0 + ty + 8*j) * DD + n0 + tx];
    __syncthreads();
    #pragma unroll
    for (int j = 0; j < 4; j++) {
        int n = n0 + ty + 8*j;
        int k = k0 + tx;
        D[(size_t)n * DD + kperm(k)] = f2tf32(tile[tx][ty + 8*j]);
    }
}

// ---------------------------------------------------------------------------
// WosWt = Wos[64,64] @ Wt[64,1024]
// ---------------------------------------------------------------------------
__global__ void woswt_kernel(const float* __restrict__ Wos, const float* __restrict__ Wt) {
    int idx = blockIdx.x * 256 + threadIdx.x;   // 65536 outputs
    int r = idx >> 10, c = idx & 1023;
    float s = 0.f;
    #pragma unroll 8
    for (int k = 0; k < 64; k++) s += Wos[r*64 + k] * Wt[k*1024 + c];
    g_WosWt[idx] = s;
}

// ---------------------------------------------------------------------------
// Spectral attention, fct query only (row-0 mask is all-True).
// ---------------------------------------------------------------------------
__global__ void spectral_kernel(const float* __restrict__ xs,
                                const float* __restrict__ Wqs,
                                const float* __restrict__ Wks,
                                const float* __restrict__ Wvs) {
    __shared__ float xs_s[FF*65];
    __shared__ float q0_s[64];
    __shared__ float qW_s[8*64];
    __shared__ float p_s[8*96];
    __shared__ float a_s[8*64];

    const int bt  = blockIdx.x;
    const int tid = threadIdx.x;   // 256
    const float* xp = xs + (size_t)bt * FF * DSS;

    for (int idx = tid; idx < FF*DSS; idx += 256)
        xs_s[(idx >> 6) * 65 + (idx & 63)] = xp[idx];
    __syncthreads();

    if (tid < 64) {
        float s = 0.f;
        #pragma unroll 8
        for (int k = 0; k < 64; k++) s += xs_s[k] * __ldg(&Wqs[k*64 + tid]);
        q0_s[tid] = s;
    }
    __syncthreads();

    for (int idx = tid; idx < 512; idx += 256) {
        int h = idx >> 6, k = idx & 63;
        float s = 0.f;
        #pragma unroll
        for (int d = 0; d < 8; d++) s += q0_s[h*8 + d] * __ldg(&Wks[k*64 + h*8 + d]);
        qW_s[idx] = s;
    }
    __syncthreads();

    const float scale = 0.35355339059327376f;   // 1/sqrt(8)
    for (int idx = tid; idx < 8*FF; idx += 256) {
        int h = idx / FF, j = idx - h * FF;
        float s = 0.f;
        #pragma unroll 8
        for (int k = 0; k < 64; k++) s += xs_s[j*65 + k] * qW_s[h*64 + k];
        p_s[h*96 + j] = s * scale;
    }
    __syncthreads();

    {
        int w = tid >> 5, lane = tid & 31;
        float m = -3.0e38f;
        for (int j = lane; j < FF; j += 32) m = fmaxf(m, p_s[w*96 + j]);
        #pragma unroll
        for (int o = 16; o > 0; o >>= 1) m = fmaxf(m, __shfl_xor_sync(0xffffffffu, m, o));
        float sum = 0.f;
        for (int j = lane; j < FF; j += 32) {
            float e = __expf(p_s[w*96 + j] - m);
            p_s[w*96 + j] = e; sum += e;
        }
        #pragma unroll
        for (int o = 16; o > 0; o >>= 1) sum += __shfl_xor_sync(0xffffffffu, sum, o);
        float inv = 1.f / sum;
        for (int j = lane; j < FF; j += 32) p_s[w*96 + j] *= inv;
    }
    __syncthreads();

    for (int idx = tid; idx < 512; idx += 256) {
        int h = idx >> 6, k = idx & 63;
        float s = 0.f;
        for (int j = 0; j < FF; j++) s += p_s[h*96 + j] * xs_s[j*65 + k];
        a_s[idx] = s;
    }
    __syncthreads();

    if (tid < 64) {
        int h = tid >> 3;
        float s = 0.f;
        #pragma unroll 8
        for (int k = 0; k < 64; k++) s += a_s[h*64 + k] * __ldg(&Wvs[k*64 + tid]);
        g_y0pre[bt*64 + tid] = s;
    }
}

// ---------------------------------------------------------------------------
// xt = x + y0pre @ WosWt  -> tf32 bits, k-permuted columns.
// 16 rows per block to amortize WosWt reads.
// ---------------------------------------------------------------------------
__global__ void __launch_bounds__(256) xt_kernel(const float* __restrict__ x) {
    const int r0  = blockIdx.x * 16;
    const int tid = threadIdx.x;     // 256
    __shared__ float y0[16][64];

    for (int idx = tid; idx < 16*64; idx += 256)
        y0[idx >> 6][idx & 63] = g_y0pre[(r0 + (idx >> 6)) * 64 + (idx & 63)];
    __syncthreads();

    const int c = tid * 4;
    float4 acc[16];
    #pragma unroll
    for (int r = 0; r < 16; r++)
        acc[r] = *(const float4*)(x + (size_t)(r0 + r) * DD + c);

    #pragma unroll 4
    for (int k = 0; k < 64; k++) {
        float4 w = *(const float4*)(g_WosWt + k * DD + c);
        #pragma unroll
        for (int r = 0; r < 16; r++) {
            float y = y0[r][k];
            acc[r].x += y * w.x; acc[r].y += y * w.y;
            acc[r].z += y * w.z; acc[r].w += y * w.w;
        }
    }
    // permuted tf32 store: element c+i -> column (c&~7) + 2i + ((c>>2)&1)
    const int base = (c & ~7) + ((c >> 2) & 1);
    #pragma unroll
    for (int r = 0; r < 16; r++) {
        uint32_t* orow = g_xt32 + (size_t)(r0 + r) * DD;
        orow[base    ] = f2tf32(acc[r].x);
        orow[base + 2] = f2tf32(acc[r].y);
        orow[base + 4] = f2tf32(acc[r].z);
        orow[base + 6] = f2tf32(acc[r].w);
    }
}

// ---------------------------------------------------------------------------
// tf32 tensor-core GEMM tile: C[128,128] = A[128,1024] @ W^T rows.
// A32: [m][k'] tf32 bits (k-permuted).  BT32: [n][k'] tf32 bits (k-permuted).
// smem both n/m-major [128][36]; fragment reads are LDS.64 pairs.
// No CVT anywhere in the loop.
// ---------------------------------------------------------------------------
__device__ __forceinline__ void gemm_tf32_tile(const uint32_t* __restrict__ A32,
                                               const uint32_t* __restrict__ BT32,
                                               float* __restrict__ C,
                                               int bm, int bn) {
    __shared__ uint32_t As[128][36];
    __shared__ uint32_t Bs[128][36];

    const int tid  = threadIdx.x;
    const int warp = tid >> 5, lane = tid & 31;
    const int wm = (warp >> 1) * 32;   // 4 warp-rows
    const int wn = (warp & 1) * 64;    // 2 warp-cols
    const int g = lane >> 2, t = lane & 3;

    const int row0 = tid >> 3;           // 0..31
    const int c4   = (tid & 7) << 2;     // 0..28

    uint4 pa[4], pb[4];
    auto loadT = [&](int k0) {
        #pragma unroll
        for (int i = 0; i < 4; i++) {
            pa[i] = *(const uint4*)(A32  + (size_t)(bm + row0 + 32*i) * 1024 + k0 + c4);
            pb[i] = *(const uint4*)(BT32 + (size_t)(bn + row0 + 32*i) * 1024 + k0 + c4);
        }
    };
    auto storeT = [&]() {
        #pragma unroll
        for (int i = 0; i < 4; i++) {
            *(uint4*)&As[row0 + 32*i][c4] = pa[i];
            *(uint4*)&Bs[row0 + 32*i][c4] = pb[i];
        }
    };

    float acc[2][8][4];
    #pragma unroll
    for (int mi = 0; mi < 2; mi++)
        #pragma unroll
        for (int ni = 0; ni < 8; ni++)
            #pragma unroll
            for (int r = 0; r < 4; r++) acc[mi][ni][r] = 0.f;

    loadT(0); storeT();
    __syncthreads();

    for (int k0 = 0; k0 < 1024; k0 += 32) {
        const bool more = (k0 + 32) < 1024;
        if (more) loadT(k0 + 32);   // overlap with mma below

        #pragma unroll
        for (int kk = 0; kk < 32; kk += 8) {
            uint32_t a[2][4], b[8][2];
            #pragma unroll
            for (int mi = 0; mi < 2; mi++) {
                int m = wm + mi * 16 + g;
                uint2 r0 = *(const uint2*)&As[m    ][kk + 2*t];  // (k=t, k=t+4)
                uint2 r1 = *(const uint2*)&As[m + 8][kk + 2*t];
                a[mi][0] = r0.x; a[mi][1] = r1.x; a[mi][2] = r0.y; a[mi][3] = r1.y;
            }
            #pragma unroll
            for (int ni = 0; ni < 8; ni++) {
                int n = wn + ni * 8 + g;
                uint2 rb = *(const uint2*)&Bs[n][kk + 2*t];
                b[ni][0] = rb.x; b[ni][1] = rb.y;
            }
            #pragma unroll
            for (int mi = 0; mi < 2; mi++)
                #pragma unroll
                for (int ni = 0; ni < 8; ni++)
                    mma_tf32(acc[mi][ni], a[mi], b[ni]);
        }
        __syncthreads();
        if (more) { storeT(); __syncthreads(); }
    }

    #pragma unroll
    for (int mi = 0; mi < 2; mi++) {
        int row0o = bm + wm + mi * 16 + g;
        #pragma unroll
        for (int ni = 0; ni < 8; ni++) {
            int col = bn + wn + ni * 8 + t * 2;
            *(float2*)(C + (size_t)row0o * 1024 + col)       = make_float2(acc[mi][ni][0], acc[mi][ni][1]);
            *(float2*)(C + (size_t)(row0o + 8) * 1024 + col) = make_float2(acc[mi][ni][2], acc[mi][ni][3]);
        }
    }
}

__global__ void __launch_bounds__(256, 2) qkv_gemm_kernel() {
    int which = blockIdx.x >> 3;                // 0..2
    int bn    = (blockIdx.x & 7) * 128;
    int bm    = blockIdx.y * 128;
    const uint32_t* W = g_wT32 + (size_t)which * DD * DD;
    float* C = g_qkv + (size_t)which * MM * DD;
    gemm_tf32_tile(g_xt32, W, C, bm, bn);
}

__global__ void __launch_bounds__(256, 2) out_gemm_kernel(float* __restrict__ C) {
    gemm_tf32_tile(g_attnout32, g_wT32 + 3 * (size_t)DD * DD, C,
                   blockIdx.y * 128, blockIdx.x * 128);
}

// ---------------------------------------------------------------------------
// Temporal attention: block-diagonal flash, STATIC smem.
// Writes tf32 bits (k-permuted) for the output GEMM.
// ---------------------------------------------------------------------------
__global__ void __launch_bounds__(256) temporal_attn_kernel(const int* __restrict__ valid_len) {
    __shared__ float Qs [32][132];
    __shared__ float KVs[32][132];
    __shared__ float Ss [32][33];
    __shared__ float m_s[32], l_s[32], al_s[32];
    __shared__ int   lo_s[32], hi_s[32];

    const int qt = blockIdx.x, h = blockIdx.y, b = blockIdx.z;
    const int tid = threadIdx.x;
    const int q0 = qt * 32;
    const float* Q = g_qkv;
    const float* K = g_qkv + (size_t)MM * DD;
    const float* V = g_qkv + 2 * (size_t)MM * DD;
    const int l = valid_len[b];

    if (tid < 32) {
        int i = q0 + tid;
        int lo, hi;
        const int dv = (h >> 1) + 1;
        if (i < l) {
            int c = (i * dv) / l;
            lo = (c * l + dv - 1) / dv;
            hi = ((c + 1) * l - 1) / dv + 1;
            if (hi > l) hi = l;
        } else { lo = l; hi = TT; }
        lo_s[tid] = lo; hi_s[tid] = hi;
        m_s[tid] = -1e30f; l_s[tid] = 0.f;
    }
    for (int f = tid; f < 32*32; f += 256) {
        int r = f >> 5, c4 = (f & 31) << 2;
        *(float4*)&Qs[r][c4] =
            *(const float4*)(Q + (size_t)(b*TT + q0 + r)*DD + h*128 + c4);
    }
    __syncthreads();
    const int bLo = lo_s[0], bHi = hi_s[31];   // lo/hi monotone in i

    const int qg = tid >> 4;   // 0..15
    const int kg = tid & 15;   // also dg for PV phase
    const float scale = 0.08838834764831845f;  // 1/sqrt(128)

    float O[2][8];
    #pragma unroll
    for (int i = 0; i < 2; i++)
        #pragma unroll
        for (int d = 0; d < 8; d++) O[i][d] = 0.f;

    for (int kt = bLo & ~31; kt < bHi; kt += 32) {
        for (int f = tid; f < 32*32; f += 256) {
            int r = f >> 5, c4 = (f & 31) << 2;
            int j = kt + r; if (j > TT - 1) j = TT - 1;
            *(float4*)&KVs[r][c4] =
                *(const float4*)(K + (size_t)(b*TT + j)*DD + h*128 + c4);
        }
        __syncthreads();

        float sacc[2][2];
        sacc[0][0] = sacc[0][1] = sacc[1][0] = sacc[1][1] = 0.f;
        #pragma unroll 8
        for (int d4 = 0; d4 < 32; d4++) {
            float4 kv0 = *(float4*)&KVs[kg][d4*4];
            float4 kv1 = *(float4*)&KVs[kg + 16][d4*4];
            #pragma unroll
            for (int i = 0; i < 2; i++) {
                float4 qv = *(float4*)&Qs[qg + 16*i][d4*4];
                sacc[i][0] += qv.x*kv0.x + qv.y*kv0.y + qv.z*kv0.z + qv.w*kv0.w;
                sacc[i][1] += qv.x*kv1.x + qv.y*kv1.y + qv.z*kv1.z + qv.w*kv1.w;
            }
        }
        #pragma unroll
        for (int i = 0; i < 2; i++) {
            Ss[qg + 16*i][kg]      = sacc[i][0] * scale;
            Ss[qg + 16*i][kg + 16] = sacc[i][1] * scale;
        }
        __syncthreads();

        if (tid < 32) {
            const int lo = lo_s[tid], hi = hi_s[tid];
            float mo = m_s[tid];
            float rmax = -3e38f;
            #pragma unroll 8
            for (int j = 0; j < 32; j++) {
                int jg = kt + j;
                float s = (jg >= lo && jg < hi) ? Ss[tid][j] : -3e38f;
                Ss[tid][j] = s;
                rmax = fmaxf(rmax, s);
            }
            float mn = fmaxf(mo, rmax);
            float alpha = __expf(mo - mn);
            float rs = 0.f;
            #pragma unroll 8
            for (int j = 0; j < 32; j++) {
                float p = __expf(Ss[tid][j] - mn);
                Ss[tid][j] = p;
                rs += p;
            }
            l_s[tid] = l_s[tid] * alpha + rs;
            m_s[tid] = mn;
            al_s[tid] = alpha;
        }
        for (int f = tid; f < 32*32; f += 256) {
            int r = f >> 5, c4 = (f & 31) << 2;
            int j = kt + r; if (j > TT - 1) j = TT - 1;
            *(float4*)&KVs[r][c4] =
                *(const float4*)(V + (size_t)(b*TT + j)*DD + h*128 + c4);
        }
        __syncthreads();

        #pragma unroll
        for (int i = 0; i < 2; i++) {
            float a = al_s[qg + 16*i];
            #pragma unroll
            for (int d = 0; d < 8; d++) O[i][d] *= a;
        }
        #pragma unroll 4
        for (int k = 0; k < 32; k++) {
            float vv[8];
            #pragma unroll
            for (int ii = 0; ii < 8; ii++) vv[ii] = KVs[k][kg + 16*ii];
            #pragma unroll
            for (int i = 0; i < 2; i++) {
                float p = Ss[qg + 16*i][k];
                #pragma unroll
                for (int ii = 0; ii < 8; ii++) O[i][ii] += p * vv[ii];
            }
        }
        __syncthreads();
    }

    // write permuted tf32 bits
    #pragma unroll
    for (int i = 0; i < 2; i++) {
        int q = q0 + qg + 16*i;
        float inv = 1.f / l_s[qg + 16*i];
        uint32_t* op = g_attnout32 + (size_t)(b*TT + q)*DD;
        #pragma unroll
        for (int ii = 0; ii < 8; ii++) {
            int col = h*128 + kg + 16*ii;
            op[kperm(col)] = f2tf32(O[i][ii] * inv);
        }
    }
}

// ---------------------------------------------------------------------------
extern "C" void kernel_launch(void* const* d_in, const int* in_sizes, int n_in,
                              void* d_out, int out_size) {
    const float* x   = (const float*)d_in[0];
    const float* xs  = (const float*)d_in[1];
    const int*   vl  = (const int*)  d_in[2];
    const float* Wq  = (const float*)d_in[3];
    const float* Wk  = (const float*)d_in[4];
    const float* Wv  = (const float*)d_in[5];
    const float* Wo  = (const float*)d_in[6];
    const float* Wqs = (const float*)d_in[7];
    const float* Wks = (const float*)d_in[8];
    const float* Wvs = (const float*)d_in[9];
    const float* Wos = (const float*)d_in[10];
    const float* Wt  = (const float*)d_in[11];
    float* out = (float*)d_out;

    prep_weights_kernel<<<dim3(32, 32, 4), dim3(32, 8)>>>(Wq, Wk, Wv, Wo);
    woswt_kernel<<<256, 256>>>(Wos, Wt);
    spectral_kernel<<<MM, 256>>>(xs, Wqs, Wks, Wvs);
    xt_kernel<<<MM/16, 256>>>(x);
    qkv_gemm_kernel<<<dim3(24, 16), 256>>>();
    temporal_attn_kernel<<<dim3(TT/32, HH, BB), 256>>>(vl);
    out_gemm_kernel<<<dim3(8, 16), 256>>>(out);
}

// round 7
// speedup vs baseline: 1.3838x; 1.3838x over previous
#include <cuda_runtime.h>
#include <cstdint>

// Shapes (fixed by the problem)
#define BB   4
#define TT   512
#define FF   93
#define DSS  64
#define DD   1024
#define HH   8
#define MM   (BB*TT)      // 2048 rows

// Scratch (static device allocations; no cudaMalloc allowed)
__device__ float    g_y0pre[MM*DSS];      // spectral fct output pre-Wos  [2048,64]
__device__ float    g_WosWt[DSS*DD];      // Wos @ Wt                     [64,1024]
__device__ float    g_xt[MM*DD];          // temporal stream input        [2048,1024]
__device__ uint32_t g_qkv32[3*MM*DD];     // Q,K,V as tf32 bit patterns
__device__ float    g_attnout[MM*DD];     // temporal attention output    [2048,1024]

// ---------------------------------------------------------------------------
// helpers: tf32 convert + mma
// ---------------------------------------------------------------------------
__device__ __forceinline__ uint32_t f2tf32(float x) {
    uint32_t r;
    asm("cvt.rna.tf32.f32 %0, %1;" : "=r"(r) : "f"(x));
    return r;
}
__device__ __forceinline__ void mma_tf32(float c[4], const uint32_t a[4], const uint32_t b[2]) {
    asm volatile(
        "mma.sync.aligned.m16n8k8.row.col.f32.tf32.tf32.f32 "
        "{%0,%1,%2,%3}, {%4,%5,%6,%7}, {%8,%9}, {%0,%1,%2,%3};"
        : "+f"(c[0]), "+f"(c[1]), "+f"(c[2]), "+f"(c[3])
        : "r"(a[0]), "r"(a[1]), "r"(a[2]), "r"(a[3]), "r"(b[0]), "r"(b[1]));
}

// ---------------------------------------------------------------------------
// WosWt = Wos[64,64] @ Wt[64,1024]
// ---------------------------------------------------------------------------
__global__ void woswt_kernel(const float* __restrict__ Wos, const float* __restrict__ Wt) {
    int idx = blockIdx.x * 256 + threadIdx.x;   // 65536 outputs
    int r = idx >> 10, c = idx & 1023;
    float s = 0.f;
    #pragma unroll 8
    for (int k = 0; k < 64; k++) s += Wos[r*64 + k] * Wt[k*1024 + c];
    g_WosWt[idx] = s;
}

// ---------------------------------------------------------------------------
// Spectral attention, fct query only (row-0 mask is all-True).
// ---------------------------------------------------------------------------
__global__ void spectral_kernel(const float* __restrict__ xs,
                                const float* __restrict__ Wqs,
                                const float* __restrict__ Wks,
                                const float* __restrict__ Wvs) {
    __shared__ float xs_s[FF*65];
    __shared__ float q0_s[64];
    __shared__ float qW_s[8*64];
    __shared__ float p_s[8*96];
    __shared__ float a_s[8*64];

    const int bt  = blockIdx.x;
    const int tid = threadIdx.x;   // 256
    const float* xp = xs + (size_t)bt * FF * DSS;

    for (int idx = tid; idx < FF*DSS; idx += 256)
        xs_s[(idx >> 6) * 65 + (idx & 63)] = xp[idx];
    __syncthreads();

    if (tid < 64) {
        float s = 0.f;
        #pragma unroll 8
        for (int k = 0; k < 64; k++) s += xs_s[k] * __ldg(&Wqs[k*64 + tid]);
        q0_s[tid] = s;
    }
    __syncthreads();

    for (int idx = tid; idx < 512; idx += 256) {
        int h = idx >> 6, k = idx & 63;
        float s = 0.f;
        #pragma unroll
        for (int d = 0; d < 8; d++) s += q0_s[h*8 + d] * __ldg(&Wks[k*64 + h*8 + d]);
        qW_s[idx] = s;
    }
    __syncthreads();

    const float scale = 0.35355339059327376f;   // 1/sqrt(8)
    for (int idx = tid; idx < 8*FF; idx += 256) {
        int h = idx / FF, j = idx - h * FF;
        float s = 0.f;
        #pragma unroll 8
        for (int k = 0; k < 64; k++) s += xs_s[j*65 + k] * qW_s[h*64 + k];
        p_s[h*96 + j] = s * scale;
    }
    __syncthreads();

    {
        int w = tid >> 5, lane = tid & 31;
        float m = -3.0e38f;
        for (int j = lane; j < FF; j += 32) m = fmaxf(m, p_s[w*96 + j]);
        #pragma unroll
        for (int o = 16; o > 0; o >>= 1) m = fmaxf(m, __shfl_xor_sync(0xffffffffu, m, o));
        float sum = 0.f;
        for (int j = lane; j < FF; j += 32) {
            float e = __expf(p_s[w*96 + j] - m);
            p_s[w*96 + j] = e; sum += e;
        }
        #pragma unroll
        for (int o = 16; o > 0; o >>= 1) sum += __shfl_xor_sync(0xffffffffu, sum, o);
        float inv = 1.f / sum;
        for (int j = lane; j < FF; j += 32) p_s[w*96 + j] *= inv;
    }
    __syncthreads();

    for (int idx = tid; idx < 512; idx += 256) {
        int h = idx >> 6, k = idx & 63;
        float s = 0.f;
        for (int j = 0; j < FF; j++) s += p_s[h*96 + j] * xs_s[j*65 + k];
        a_s[idx] = s;
    }
    __syncthreads();

    if (tid < 64) {
        int h = tid >> 3;
        float s = 0.f;
        #pragma unroll 8
        for (int k = 0; k < 64; k++) s += a_s[h*64 + k] * __ldg(&Wvs[k*64 + tid]);
        g_y0pre[bt*64 + tid] = s;
    }
}

// ---------------------------------------------------------------------------
// xt = x + y0pre @ WosWt.  16 rows per block to amortize WosWt reads.
// ---------------------------------------------------------------------------
__global__ void __launch_bounds__(256) xt_kernel(const float* __restrict__ x) {
    const int r0  = blockIdx.x * 16;
    const int tid = threadIdx.x;     // 256
    __shared__ float y0[16][64];

    for (int idx = tid; idx < 16*64; idx += 256)
        y0[idx >> 6][idx & 63] = g_y0pre[(r0 + (idx >> 6)) * 64 + (idx & 63)];
    __syncthreads();

    const int c = tid * 4;
    float4 acc[16];
    #pragma unroll
    for (int r = 0; r < 16; r++)
        acc[r] = *(const float4*)(x + (size_t)(r0 + r) * DD + c);

    #pragma unroll 4
    for (int k = 0; k < 64; k++) {
        float4 w = *(const float4*)(g_WosWt + k * DD + c);
        #pragma unroll
        for (int r = 0; r < 16; r++) {
            float y = y0[r][k];
            acc[r].x += y * w.x; acc[r].y += y * w.y;
            acc[r].z += y * w.z; acc[r].w += y * w.w;
        }
    }
    #pragma unroll
    for (int r = 0; r < 16; r++)
        *(float4*)(g_xt + (size_t)(r0 + r) * DD + c) = acc[r];
}

// ---------------------------------------------------------------------------
// tf32 tensor-core GEMM tile (R5-proven): C[128,128] = A[128,1024] @ W[.,128]
// smem holds PRE-CONVERTED tf32 bits; scalar conflict-free fragment reads.
// CVT_OUT: store tf32 bit patterns instead of floats (for Q/K/V).
// ---------------------------------------------------------------------------
template <bool CVT_OUT>
__device__ __forceinline__ void gemm_tf32_tile(const float* __restrict__ A,
                                               const float* __restrict__ Bw,
                                               void* __restrict__ Cv,
                                               int bm, int bn) {
    __shared__ uint32_t As[128][36];   // m-major tf32 bits, pad 36
    __shared__ uint32_t Bs[32][136];   // k-major tf32 bits, pad 136

    const int tid  = threadIdx.x;
    const int warp = tid >> 5, lane = tid & 31;
    const int wm = (warp >> 1) * 32;   // 4 warp-rows
    const int wn = (warp & 1) * 64;    // 2 warp-cols
    const int g = lane >> 2, t = lane & 3;

    const int aRow0 = tid >> 3,  aC = (tid & 7) << 2;
    const int bRow0 = tid >> 5,  bC = (tid & 31) << 2;

    float4 pa[2], pa2[2], pb[4];
    auto loadA = [&](int k0) {
        pa[0]  = *(const float4*)(A + (size_t)(bm + aRow0      ) * 1024 + k0 + aC);
        pa[1]  = *(const float4*)(A + (size_t)(bm + aRow0 + 32 ) * 1024 + k0 + aC);
        pa2[0] = *(const float4*)(A + (size_t)(bm + aRow0 + 64 ) * 1024 + k0 + aC);
        pa2[1] = *(const float4*)(A + (size_t)(bm + aRow0 + 96 ) * 1024 + k0 + aC);
    };
    auto loadB = [&](int k0) {
        #pragma unroll
        for (int i = 0; i < 4; i++)
            pb[i] = *(const float4*)(Bw + (size_t)(k0 + bRow0 + 8*i) * 1024 + bn + bC);
    };
    auto storeTiles = [&]() {
        #pragma unroll
        for (int i = 0; i < 2; i++) {
            float4 v = pa[i];
            uint32_t* p = &As[aRow0 + 32*i][aC];
            p[0]=f2tf32(v.x); p[1]=f2tf32(v.y); p[2]=f2tf32(v.z); p[3]=f2tf32(v.w);
            v = pa2[i];
            p = &As[aRow0 + 64 + 32*i][aC];
            p[0]=f2tf32(v.x); p[1]=f2tf32(v.y); p[2]=f2tf32(v.z); p[3]=f2tf32(v.w);
        }
        #pragma unroll
        for (int i = 0; i < 4; i++) {
            float4 v = pb[i];
            uint32_t* p = &Bs[bRow0 + 8*i][bC];
            p[0]=f2tf32(v.x); p[1]=f2tf32(v.y); p[2]=f2tf32(v.z); p[3]=f2tf32(v.w);
        }
    };

    float acc[2][8][4];
    #pragma unroll
    for (int mi = 0; mi < 2; mi++)
        #pragma unroll
        for (int ni = 0; ni < 8; ni++)
            #pragma unroll
            for (int r = 0; r < 4; r++) acc[mi][ni][r] = 0.f;

    loadA(0); loadB(0); storeTiles();
    __syncthreads();

    for (int k0 = 0; k0 < 1024; k0 += 32) {
        const bool more = (k0 + 32) < 1024;
        if (more) { loadA(k0 + 32); loadB(k0 + 32); }

        #pragma unroll
        for (int kk = 0; kk < 32; kk += 8) {
            uint32_t a[2][4], b[8][2];
            #pragma unroll
            for (int mi = 0; mi < 2; mi++) {
                int m = wm + mi * 16 + g;
                a[mi][0] = As[m    ][kk + t];
                a[mi][1] = As[m + 8][kk + t];
                a[mi][2] = As[m    ][kk + t + 4];
                a[mi][3] = As[m + 8][kk + t + 4];
            }
            #pragma unroll
            for (int ni = 0; ni < 8; ni++) {
                int n = wn + ni * 8 + g;
                b[ni][0] = Bs[kk + t    ][n];
                b[ni][1] = Bs[kk + t + 4][n];
            }
            #pragma unroll
            for (int mi = 0; mi < 2; mi++)
                #pragma unroll
                for (int ni = 0; ni < 8; ni++)
                    mma_tf32(acc[mi][ni], a[mi], b[ni]);
        }
        __syncthreads();
        if (more) { storeTiles(); __syncthreads(); }
    }

    #pragma unroll
    for (int mi = 0; mi < 2; mi++) {
        int row0 = bm + wm + mi * 16 + g;
        #pragma unroll
        for (int ni = 0; ni < 8; ni++) {
            int col = bn + wn + ni * 8 + t * 2;
            if (CVT_OUT) {
                uint32_t* C = (uint32_t*)Cv;
                *(uint2*)(C + (size_t)row0 * 1024 + col) =
                    make_uint2(f2tf32(acc[mi][ni][0]), f2tf32(acc[mi][ni][1]));
                *(uint2*)(C + (size_t)(row0 + 8) * 1024 + col) =
                    make_uint2(f2tf32(acc[mi][ni][2]), f2tf32(acc[mi][ni][3]));
            } else {
                float* C = (float*)Cv;
                *(float2*)(C + (size_t)row0 * 1024 + col) =
                    make_float2(acc[mi][ni][0], acc[mi][ni][1]);
                *(float2*)(C + (size_t)(row0 + 8) * 1024 + col) =
                    make_float2(acc[mi][ni][2], acc[mi][ni][3]);
            }
        }
    }
}

__global__ void __launch_bounds__(256, 2) qkv_gemm_kernel(const float* __restrict__ Wq,
                                                          const float* __restrict__ Wk,
                                                          const float* __restrict__ Wv) {
    int which = blockIdx.x >> 3;                // 0..2
    int bn    = (blockIdx.x & 7) * 128;
    int bm    = blockIdx.y * 128;
    const float* W = (which == 0) ? Wq : ((which == 1) ? Wk : Wv);
    uint32_t* C = g_qkv32 + (size_t)which * MM * DD;
    gemm_tf32_tile<true>(g_xt, W, C, bm, bn);
}

__global__ void __launch_bounds__(256, 2) out_gemm_kernel(const float* __restrict__ Wo, float* __restrict__ C) {
    gemm_tf32_tile<false>(g_attnout, Wo, C, blockIdx.y * 128, blockIdx.x * 128);
}

// ---------------------------------------------------------------------------
// Temporal attention: block-diagonal flash on tf32 tensor cores.
// Block = 32 queries of one (b,h). Q/K/V already tf32 bits in gmem.
// 8 warps: S warp-tile 16x8 (M2xN4 grid), PV warp-tile 16x32 (M2xN4 grid).
// ---------------------------------------------------------------------------
__global__ void __launch_bounds__(256) temporal_attn_kernel(const int* __restrict__ valid_len) {
    __shared__ uint32_t Qs [32][132];
    __shared__ uint32_t KVs[32][132];
    __shared__ float    Ss [32][36];
    __shared__ float m_s[32], l_s[32], al_s[32];
    __shared__ int   lo_s[32], hi_s[32];

    const int qt = blockIdx.x, h = blockIdx.y, b = blockIdx.z;
    const int tid = threadIdx.x;
    const int warp = tid >> 5, lane = tid & 31;
    const int g = lane >> 2, t = lane & 3;
    const int q0 = qt * 32;
    const uint32_t* Q = g_qkv32;
    const uint32_t* K = g_qkv32 + (size_t)MM * DD;
    const uint32_t* V = g_qkv32 + 2 * (size_t)MM * DD;
    const int l = valid_len[b];

    if (tid < 32) {
        int i = q0 + tid;
        int lo, hi;
        const int dv = (h >> 1) + 1;
        if (i < l) {
            int c = (i * dv) / l;
            lo = (c * l + dv - 1) / dv;
            hi = ((c + 1) * l - 1) / dv + 1;
            if (hi > l) hi = l;
        } else { lo = l; hi = TT; }
        lo_s[tid] = lo; hi_s[tid] = hi;
        m_s[tid] = -1e30f; l_s[tid] = 0.f;
    }
    for (int f = tid; f < 32*32; f += 256) {
        int r = f >> 5, c4 = (f & 31) << 2;
        *(uint4*)&Qs[r][c4] =
            *(const uint4*)(Q + (size_t)(b*TT + q0 + r)*DD + h*128 + c4);
    }
    __syncthreads();
    const int bLo = lo_s[0], bHi = hi_s[31];   // lo/hi monotone in i

    const int wmS = (warp >> 2) * 16, wnS = (warp & 3) * 8;   // S: 16x8 per warp
    const int wmP = (warp >> 2) * 16, wnP = (warp & 3) * 32;  // PV: 16x32 per warp
    const float scale = 0.08838834764831845f;  // 1/sqrt(128)

    float O[4][4];
    #pragma unroll
    for (int ni = 0; ni < 4; ni++)
        #pragma unroll
        for (int r = 0; r < 4; r++) O[ni][r] = 0.f;

    for (int kt = bLo & ~31; kt < bHi; kt += 32) {
        // ---- load K tile (32 x 128 tf32 bits) ----
        for (int f = tid; f < 32*32; f += 256) {
            int r = f >> 5, c4 = (f & 31) << 2;
            int j = kt + r; if (j > TT - 1) j = TT - 1;
            *(uint4*)&KVs[r][c4] =
                *(const uint4*)(K + (size_t)(b*TT + j)*DD + h*128 + c4);
        }
        __syncthreads();

        // ---- S = Q @ K^T via mma (each warp: 16x8 of S, 16 k-steps) ----
        float sc[4] = {0.f, 0.f, 0.f, 0.f};
        #pragma unroll
        for (int kk = 0; kk < 128; kk += 8) {
            uint32_t a[4], bb[2];
            a[0] = Qs[wmS + g    ][kk + t];
            a[1] = Qs[wmS + g + 8][kk + t];
            a[2] = Qs[wmS + g    ][kk + t + 4];
            a[3] = Qs[wmS + g + 8][kk + t + 4];
            bb[0] = KVs[wnS + g][kk + t];
            bb[1] = KVs[wnS + g][kk + t + 4];
            mma_tf32(sc, a, bb);
        }
        Ss[wmS + g    ][wnS + 2*t    ] = sc[0] * scale;
        Ss[wmS + g    ][wnS + 2*t + 1] = sc[1] * scale;
        Ss[wmS + g + 8][wnS + 2*t    ] = sc[2] * scale;
        Ss[wmS + g + 8][wnS + 2*t + 1] = sc[3] * scale;
        __syncthreads();

        // ---- softmax bookkeeping (one thread per query row) ----
        if (tid < 32) {
            const int lo = lo_s[tid], hi = hi_s[tid];
            float mo = m_s[tid];
            float rmax = -3e38f;
            #pragma unroll 8
            for (int j = 0; j < 32; j++) {
                int jg = kt + j;
                float s = (jg >= lo && jg < hi) ? Ss[tid][j] : -3e38f;
                Ss[tid][j] = s;
                rmax = fmaxf(rmax, s);
            }
            float mn = fmaxf(mo, rmax);
            float alpha = __expf(mo - mn);
            float rs = 0.f;
            #pragma unroll 8
            for (int j = 0; j < 32; j++) {
                float p = __expf(Ss[tid][j] - mn);
                Ss[tid][j] = p;
                rs += p;
            }
            l_s[tid] = l_s[tid] * alpha + rs;
            m_s[tid] = mn;
            al_s[tid] = alpha;
        }
        // ---- load V tile into the same buffer (K consumed) ----
        for (int f = tid; f < 32*32; f += 256) {
            int r = f >> 5, c4 = (f & 31) << 2;
            int j = kt + r; if (j > TT - 1) j = TT - 1;
            *(uint4*)&KVs[r][c4] =
                *(const uint4*)(V + (size_t)(b*TT + j)*DD + h*128 + c4);
        }
        __syncthreads();

        // ---- rescale O, then O += P @ V via mma ----
        {
            float a0 = al_s[wmP + g], a1 = al_s[wmP + g + 8];
            #pragma unroll
            for (int ni = 0; ni < 4; ni++) {
                O[ni][0] *= a0; O[ni][1] *= a0;
                O[ni][2] *= a1; O[ni][3] *= a1;
            }
        }
        #pragma unroll
        for (int kk = 0; kk < 32; kk += 8) {
            uint32_t a[4];
            a[0] = f2tf32(Ss[wmP + g    ][kk + t]);
            a[1] = f2tf32(Ss[wmP + g + 8][kk + t]);
            a[2] = f2tf32(Ss[wmP + g    ][kk + t + 4]);
            a[3] = f2tf32(Ss[wmP + g + 8][kk + t + 4]);
            #pragma unroll
            for (int ni = 0; ni < 4; ni++) {
                uint32_t bb[2];
                int n = wnP + ni * 8 + g;
                bb[0] = KVs[kk + t    ][n];
                bb[1] = KVs[kk + t + 4][n];
                mma_tf32(O[ni], a, bb);
            }
        }
        __syncthreads();
    }

    // epilogue: divide by l, write float
    {
        float inv0 = 1.f / l_s[wmP + g];
        float inv1 = 1.f / l_s[wmP + g + 8];
        const size_t r0 = (size_t)(b*TT + q0 + wmP + g) * DD;
        const size_t r1 = (size_t)(b*TT + q0 + wmP + g + 8) * DD;
        #pragma unroll
        for (int ni = 0; ni < 4; ni++) {
            int col = h*128 + wnP + ni*8 + 2*t;
            *(float2*)(g_attnout + r0 + col) = make_float2(O[ni][0]*inv0, O[ni][1]*inv0);
            *(float2*)(g_attnout + r1 + col) = make_float2(O[ni][2]*inv1, O[ni][3]*inv1);
        }
    }
}

// ---------------------------------------------------------------------------
extern "C" void kernel_launch(void* const* d_in, const int* in_sizes, int n_in,
                              void* d_out, int out_size) {
    const float* x   = (const float*)d_in[0];
    const float* xs  = (const float*)d_in[1];
    const int*   vl  = (const int*)  d_in[2];
    const float* Wq  = (const float*)d_in[3];
    const float* Wk  = (const float*)d_in[4];
    const float* Wv  = (const float*)d_in[5];
    const float* Wo  = (const float*)d_in[6];
    const float* Wqs = (const float*)d_in[7];
    const float* Wks = (const float*)d_in[8];
    const float* Wvs = (const float*)d_in[9];
    const float* Wos = (const float*)d_in[10];
    const float* Wt  = (const float*)d_in[11];
    float* out = (float*)d_out;

    woswt_kernel<<<256, 256>>>(Wos, Wt);
    spectral_kernel<<<MM, 256>>>(xs, Wqs, Wks, Wvs);
    xt_kernel<<<MM/16, 256>>>(x);
    qkv_gemm_kernel<<<dim3(24, 16), 256>>>(Wq, Wk, Wv);
    temporal_attn_kernel<<<dim3(TT/32, HH, BB), 256>>>(vl);
    out_gemm_kernel<<<dim3(8, 16), 256>>>(Wo, out);
}

// round 8
// speedup vs baseline: 1.3996x; 1.0114x over previous
#include <cuda_runtime.h>
#include <cstdint>

// Shapes (fixed by the problem)
#define BB   4
#define TT   512
#define FF   93
#define DSS  64
#define DD   1024
#define HH   8
#define MM   (BB*TT)      // 2048 rows

// Scratch (static device allocations; no cudaMalloc allowed)
__device__ float    g_y0pre[MM*DSS];      // spectral fct output pre-Wos  [2048,64]
__device__ float    g_WosWt[DSS*DD];      // Wos @ Wt                     [64,1024]
__device__ uint32_t g_xt32[MM*DD];        // temporal input, tf32 bits (plain [m][k])
__device__ uint32_t g_w32[4*DD*DD];       // Wq,Wk,Wv,Wo tf32 bits (plain [k][n])
__device__ uint32_t g_qkv32[3*MM*DD];     // Q,K,V as tf32 bit patterns
__device__ uint32_t g_attnout32[MM*DD];   // attention out, tf32 bits (plain [m][k])

// ---------------------------------------------------------------------------
// helpers: tf32 convert + mma
// ---------------------------------------------------------------------------
__device__ __forceinline__ uint32_t f2tf32(float x) {
    uint32_t r;
    asm("cvt.rna.tf32.f32 %0, %1;" : "=r"(r) : "f"(x));
    return r;
}
__device__ __forceinline__ void mma_tf32(float c[4], const uint32_t a[4], const uint32_t b[2]) {
    asm volatile(
        "mma.sync.aligned.m16n8k8.row.col.f32.tf32.tf32.f32 "
        "{%0,%1,%2,%3}, {%4,%5,%6,%7}, {%8,%9}, {%0,%1,%2,%3};"
        : "+f"(c[0]), "+f"(c[1]), "+f"(c[2]), "+f"(c[3])
        : "r"(a[0]), "r"(a[1]), "r"(a[2]), "r"(a[3]), "r"(b[0]), "r"(b[1]));
}

// ---------------------------------------------------------------------------
// prep: convert weights (same [k][n] layout) to tf32 bits.
// grid (4096, 4), block 256
// ---------------------------------------------------------------------------
__global__ void prep_w_kernel(const float* __restrict__ Wq,
                              const float* __restrict__ Wk,
                              const float* __restrict__ Wv,
                              const float* __restrict__ Wo) {
    const int z = blockIdx.y;
    const float* S = (z == 0) ? Wq : (z == 1) ? Wk : (z == 2) ? Wv : Wo;
    int i = blockIdx.x * 256 + threadIdx.x;
    g_w32[(size_t)z * DD * DD + i] = f2tf32(S[i]);
}

// ---------------------------------------------------------------------------
// WosWt = Wos[64,64] @ Wt[64,1024]
// ---------------------------------------------------------------------------
__global__ void woswt_kernel(const float* __restrict__ Wos, const float* __restrict__ Wt) {
    int idx = blockIdx.x * 256 + threadIdx.x;   // 65536 outputs
    int r = idx >> 10, c = idx & 1023;
    float s = 0.f;
    #pragma unroll 8
    for (int k = 0; k < 64; k++) s += Wos[r*64 + k] * Wt[k*1024 + c];
    g_WosWt[idx] = s;
}

// ---------------------------------------------------------------------------
// Spectral attention, fct query only (row-0 mask is all-True).
// xs_s stride 68 (16B-aligned rows) for float4 score dot-products.
// ---------------------------------------------------------------------------
__global__ void spectral_kernel(const float* __restrict__ xs,
                                const float* __restrict__ Wqs,
                                const float* __restrict__ Wks,
                                const float* __restrict__ Wvs) {
    __shared__ float xs_s[FF*68];
    __shared__ float q0_s[64];
    __shared__ float qW_s[8*64];
    __shared__ float p_s[8*96];
    __shared__ float a_s[8*64];

    const int bt  = blockIdx.x;
    const int tid = threadIdx.x;   // 256
    const float* xp = xs + (size_t)bt * FF * DSS;

    for (int idx = tid; idx < FF*DSS; idx += 256)
        xs_s[(idx >> 6) * 68 + (idx & 63)] = xp[idx];
    __syncthreads();

    if (tid < 64) {
        float s = 0.f;
        #pragma unroll 8
        for (int k = 0; k < 64; k++) s += xs_s[k] * __ldg(&Wqs[k*64 + tid]);
        q0_s[tid] = s;
    }
    __syncthreads();

    // qW[h][k] = sum_d q0[h*8+d] * Wks[k][h*8+d]
    for (int idx = tid; idx < 512; idx += 256) {
        int h = idx >> 6, k = idx & 63;
        float s = 0.f;
        #pragma unroll
        for (int d = 0; d < 8; d++) s += q0_s[h*8 + d] * __ldg(&Wks[k*64 + h*8 + d]);
        qW_s[idx] = s;
    }
    __syncthreads();

    const float scale = 0.35355339059327376f;   // 1/sqrt(8)
    for (int idx = tid; idx < 8*FF; idx += 256) {
        int h = idx / FF, j = idx - h * FF;
        const float* xr = &xs_s[j*68];
        const float* qr = &qW_s[h*64];
        float s = 0.f;
        #pragma unroll
        for (int k4 = 0; k4 < 16; k4++) {
            float4 a = *(const float4*)(xr + k4*4);
            float4 w = *(const float4*)(qr + k4*4);
            s += a.x*w.x + a.y*w.y + a.z*w.z + a.w*w.w;
        }
        p_s[h*96 + j] = s * scale;
    }
    __syncthreads();

    {
        int w = tid >> 5, lane = tid & 31;
        float m = -3.0e38f;
        for (int j = lane; j < FF; j += 32) m = fmaxf(m, p_s[w*96 + j]);
        #pragma unroll
        for (int o = 16; o > 0; o >>= 1) m = fmaxf(m, __shfl_xor_sync(0xffffffffu, m, o));
        float sum = 0.f;
        for (int j = lane; j < FF; j += 32) {
            float e = __expf(p_s[w*96 + j] - m);
            p_s[w*96 + j] = e; sum += e;
        }
        #pragma unroll
        for (int o = 16; o > 0; o >>= 1) sum += __shfl_xor_sync(0xffffffffu, sum, o);
        float inv = 1.f / sum;
        for (int j = lane; j < FF; j += 32) p_s[w*96 + j] *= inv;
    }
    __syncthreads();

    for (int idx = tid; idx < 512; idx += 256) {
        int h = idx >> 6, k = idx & 63;
        float s = 0.f;
        for (int j = 0; j < FF; j++) s += p_s[h*96 + j] * xs_s[j*68 + k];
        a_s[idx] = s;
    }
    __syncthreads();

    if (tid < 64) {
        int h = tid >> 3;
        float s = 0.f;
        #pragma unroll 8
        for (int k = 0; k < 64; k++) s += a_s[h*64 + k] * __ldg(&Wvs[k*64 + tid]);
        g_y0pre[bt*64 + tid] = s;
    }
}

// ---------------------------------------------------------------------------
// xt = x + y0pre @ WosWt -> tf32 bits (plain layout).
// 16 rows per block to amortize WosWt reads.
// ---------------------------------------------------------------------------
__global__ void __launch_bounds__(256) xt_kernel(const float* __restrict__ x) {
    const int r0  = blockIdx.x * 16;
    const int tid = threadIdx.x;     // 256
    __shared__ float y0[16][64];

    for (int idx = tid; idx < 16*64; idx += 256)
        y0[idx >> 6][idx & 63] = g_y0pre[(r0 + (idx >> 6)) * 64 + (idx & 63)];
    __syncthreads();

    const int c = tid * 4;
    float4 acc[16];
    #pragma unroll
    for (int r = 0; r < 16; r++)
        acc[r] = *(const float4*)(x + (size_t)(r0 + r) * DD + c);

    #pragma unroll 4
    for (int k = 0; k < 64; k++) {
        float4 w = *(const float4*)(g_WosWt + k * DD + c);
        #pragma unroll
        for (int r = 0; r < 16; r++) {
            float y = y0[r][k];
            acc[r].x += y * w.x; acc[r].y += y * w.y;
            acc[r].z += y * w.z; acc[r].w += y * w.w;
        }
    }
    #pragma unroll
    for (int r = 0; r < 16; r++) {
        uint4 bits = make_uint4(f2tf32(acc[r].x), f2tf32(acc[r].y),
                                f2tf32(acc[r].z), f2tf32(acc[r].w));
        *(uint4*)(g_xt32 + (size_t)(r0 + r) * DD + c) = bits;
    }
}

// ---------------------------------------------------------------------------
// tf32 tensor-core GEMM tile: C[128,128] = A[128,1024] @ W[.,128]
// A and B are PRE-CONVERTED tf32 bits in gmem; fill = LDG.128 + STS.128 only.
// CVT_OUT: store tf32 bit patterns instead of floats (for Q/K/V).
// ---------------------------------------------------------------------------
template <bool CVT_OUT>
__device__ __forceinline__ void gemm_tf32_tile(const uint32_t* __restrict__ A32,
                                               const uint32_t* __restrict__ B32,
                                               void* __restrict__ Cv,
                                               int bm, int bn) {
    __shared__ uint32_t As[128][36];   // m-major tf32 bits, pad 36
    __shared__ uint32_t Bs[32][136];   // k-major tf32 bits, pad 136

    const int tid  = threadIdx.x;
    const int warp = tid >> 5, lane = tid & 31;
    const int wm = (warp >> 1) * 32;   // 4 warp-rows
    const int wn = (warp & 1) * 64;    // 2 warp-cols
    const int g = lane >> 2, t = lane & 3;

    const int aRow0 = tid >> 3,  aC = (tid & 7) << 2;
    const int bRow0 = tid >> 5,  bC = (tid & 31) << 2;

    uint4 pa[4], pb[4];
    auto loadA = [&](int k0) {
        #pragma unroll
        for (int i = 0; i < 4; i++)
            pa[i] = *(const uint4*)(A32 + (size_t)(bm + aRow0 + 32*i) * 1024 + k0 + aC);
    };
    auto loadB = [&](int k0) {
        #pragma unroll
        for (int i = 0; i < 4; i++)
            pb[i] = *(const uint4*)(B32 + (size_t)(k0 + bRow0 + 8*i) * 1024 + bn + bC);
    };
    auto storeTiles = [&]() {
        #pragma unroll
        for (int i = 0; i < 4; i++) *(uint4*)&As[aRow0 + 32*i][aC] = pa[i];
        #pragma unroll
        for (int i = 0; i < 4; i++) *(uint4*)&Bs[bRow0 + 8*i][bC] = pb[i];
    };

    float acc[2][8][4];
    #pragma unroll
    for (int mi = 0; mi < 2; mi++)
        #pragma unroll
        for (int ni = 0; ni < 8; ni++)
            #pragma unroll
            for (int r = 0; r < 4; r++) acc[mi][ni][r] = 0.f;

    loadA(0); loadB(0); storeTiles();
    __syncthreads();

    for (int k0 = 0; k0 < 1024; k0 += 32) {
        const bool more = (k0 + 32) < 1024;
        if (more) { loadA(k0 + 32); loadB(k0 + 32); }

        #pragma unroll
        for (int kk = 0; kk < 32; kk += 8) {
            uint32_t a[2][4], b[8][2];
            #pragma unroll
            for (int mi = 0; mi < 2; mi++) {
                int m = wm + mi * 16 + g;
                a[mi][0] = As[m    ][kk + t];
                a[mi][1] = As[m + 8][kk + t];
                a[mi][2] = As[m    ][kk + t + 4];
                a[mi][3] = As[m + 8][kk + t + 4];
            }
            #pragma unroll
            for (int ni = 0; ni < 8; ni++) {
                int n = wn + ni * 8 + g;
                b[ni][0] = Bs[kk + t    ][n];
                b[ni][1] = Bs[kk + t + 4][n];
            }
            #pragma unroll
            for (int mi = 0; mi < 2; mi++)
                #pragma unroll
                for (int ni = 0; ni < 8; ni++)
                    mma_tf32(acc[mi][ni], a[mi], b[ni]);
        }
        __syncthreads();
        if (more) { storeTiles(); __syncthreads(); }
    }

    #pragma unroll
    for (int mi = 0; mi < 2; mi++) {
        int row0 = bm + wm + mi * 16 + g;
        #pragma unroll
        for (int ni = 0; ni < 8; ni++) {
            int col = bn + wn + ni * 8 + t * 2;
            if (CVT_OUT) {
                uint32_t* C = (uint32_t*)Cv;
                *(uint2*)(C + (size_t)row0 * 1024 + col) =
                    make_uint2(f2tf32(acc[mi][ni][0]), f2tf32(acc[mi][ni][1]));
                *(uint2*)(C + (size_t)(row0 + 8) * 1024 + col) =
                    make_uint2(f2tf32(acc[mi][ni][2]), f2tf32(acc[mi][ni][3]));
            } else {
                float* C = (float*)Cv;
                *(float2*)(C + (size_t)row0 * 1024 + col) =
                    make_float2(acc[mi][ni][0], acc[mi][ni][1]);
                *(float2*)(C + (size_t)(row0 + 8) * 1024 + col) =
                    make_float2(acc[mi][ni][2], acc[mi][ni][3]);
            }
        }
    }
}

__global__ void __launch_bounds__(256, 2) qkv_gemm_kernel() {
    int which = blockIdx.x >> 3;                // 0..2
    int bn    = (blockIdx.x & 7) * 128;
    int bm    = blockIdx.y * 128;
    const uint32_t* W = g_w32 + (size_t)which * DD * DD;
    uint32_t* C = g_qkv32 + (size_t)which * MM * DD;
    gemm_tf32_tile<true>(g_xt32, W, C, bm, bn);
}

__global__ void __launch_bounds__(256, 2) out_gemm_kernel(float* __restrict__ C) {
    gemm_tf32_tile<false>(g_attnout32, g_w32 + 3 * (size_t)DD * DD, C,
                          blockIdx.y * 128, blockIdx.x * 128);
}

// ---------------------------------------------------------------------------
// Temporal attention: block-diagonal flash on tf32 tensor cores.
// Block = 32 queries of one (b,h). Q/K/V already tf32 bits in gmem.
// 8 warps: S warp-tile 16x8 (M2xN4 grid), PV warp-tile 16x32 (M2xN4 grid).
// ---------------------------------------------------------------------------
__global__ void __launch_bounds__(256) temporal_attn_kernel(const int* __restrict__ valid_len) {
    __shared__ uint32_t Qs [32][132];
    __shared__ uint32_t KVs[32][132];
    __shared__ float    Ss [32][36];
    __shared__ float m_s[32], l_s[32], al_s[32];
    __shared__ int   lo_s[32], hi_s[32];

    const int qt = blockIdx.x, h = blockIdx.y, b = blockIdx.z;
    const int tid = threadIdx.x;
    const int warp = tid >> 5, lane = tid & 31;
    const int g = lane >> 2, t = lane & 3;
    const int q0 = qt * 32;
    const uint32_t* Q = g_qkv32;
    const uint32_t* K = g_qkv32 + (size_t)MM * DD;
    const uint32_t* V = g_qkv32 + 2 * (size_t)MM * DD;
    const int l = valid_len[b];

    if (tid < 32) {
        int i = q0 + tid;
        int lo, hi;
        const int dv = (h >> 1) + 1;
        if (i < l) {
            int c = (i * dv) / l;
            lo = (c * l + dv - 1) / dv;
            hi = ((c + 1) * l - 1) / dv + 1;
            if (hi > l) hi = l;
        } else { lo = l; hi = TT; }
        lo_s[tid] = lo; hi_s[tid] = hi;
        m_s[tid] = -1e30f; l_s[tid] = 0.f;
    }
    for (int f = tid; f < 32*32; f += 256) {
        int r = f >> 5, c4 = (f & 31) << 2;
        *(uint4*)&Qs[r][c4] =
            *(const uint4*)(Q + (size_t)(b*TT + q0 + r)*DD + h*128 + c4);
    }
    __syncthreads();
    const int bLo = lo_s[0], bHi = hi_s[31];   // lo/hi monotone in i

    const int wmS = (warp >> 2) * 16, wnS = (warp & 3) * 8;   // S: 16x8 per warp
    const int wmP = (warp >> 2) * 16, wnP = (warp & 3) * 32;  // PV: 16x32 per warp
    const float scale = 0.08838834764831845f;  // 1/sqrt(128)

    float O[4][4];
    #pragma unroll
    for (int ni = 0; ni < 4; ni++)
        #pragma unroll
        for (int r = 0; r < 4; r++) O[ni][r] = 0.f;

    for (int kt = bLo & ~31; kt < bHi; kt += 32) {
        // ---- load K tile (32 x 128 tf32 bits) ----
        for (int f = tid; f < 32*32; f += 256) {
            int r = f >> 5, c4 = (f & 31) << 2;
            int j = kt + r; if (j > TT - 1) j = TT - 1;
            *(uint4*)&KVs[r][c4] =
                *(const uint4*)(K + (size_t)(b*TT + j)*DD + h*128 + c4);
        }
        __syncthreads();

        // ---- S = Q @ K^T via mma (each warp: 16x8 of S, 16 k-steps) ----
        float sc[4] = {0.f, 0.f, 0.f, 0.f};
        #pragma unroll
        for (int kk = 0; kk < 128; kk += 8) {
            uint32_t a[4], bb[2];
            a[0] = Qs[wmS + g    ][kk + t];
            a[1] = Qs[wmS + g + 8][kk + t];
            a[2] = Qs[wmS + g    ][kk + t + 4];
            a[3] = Qs[wmS + g + 8][kk + t + 4];
            bb[0] = KVs[wnS + g][kk + t];
            bb[1] = KVs[wnS + g][kk + t + 4];
            mma_tf32(sc, a, bb);
        }
        Ss[wmS + g    ][wnS + 2*t    ] = sc[0] * scale;
        Ss[wmS + g    ][wnS + 2*t + 1] = sc[1] * scale;
        Ss[wmS + g + 8][wnS + 2*t    ] = sc[2] * scale;
        Ss[wmS + g + 8][wnS + 2*t + 1] = sc[3] * scale;
        __syncthreads();

        // ---- softmax bookkeeping (one thread per query row) ----
        if (tid < 32) {
            const int lo = lo_s[tid], hi = hi_s[tid];
            float mo = m_s[tid];
            float rmax = -3e38f;
            #pragma unroll 8
            for (int j = 0; j < 32; j++) {
                int jg = kt + j;
                float s = (jg >= lo && jg < hi) ? Ss[tid][j] : -3e38f;
                Ss[tid][j] = s;
                rmax = fmaxf(rmax, s);
            }
            float mn = fmaxf(mo, rmax);
            float alpha = __expf(mo - mn);
            float rs = 0.f;
            #pragma unroll 8
            for (int j = 0; j < 32; j++) {
                float p = __expf(Ss[tid][j] - mn);
                Ss[tid][j] = p;
                rs += p;
            }
            l_s[tid] = l_s[tid] * alpha + rs;
            m_s[tid] = mn;
            al_s[tid] = alpha;
        }
        // ---- load V tile into the same buffer (K consumed) ----
        for (int f = tid; f < 32*32; f += 256) {
            int r = f >> 5, c4 = (f & 31) << 2;
            int j = kt + r; if (j > TT - 1) j = TT - 1;
            *(uint4*)&KVs[r][c4] =
                *(const uint4*)(V + (size_t)(b*TT + j)*DD + h*128 + c4);
        }
        __syncthreads();

        // ---- rescale O, then O += P @ V via mma ----
        {
            float a0 = al_s[wmP + g], a1 = al_s[wmP + g + 8];
            #pragma unroll
            for (int ni = 0; ni < 4; ni++) {
                O[ni][0] *= a0; O[ni][1] *= a0;
                O[ni][2] *= a1; O[ni][3] *= a1;
            }
        }
        #pragma unroll
        for (int kk = 0; kk < 32; kk += 8) {
            uint32_t a[4];
            a[0] = f2tf32(Ss[wmP + g    ][kk + t]);
            a[1] = f2tf32(Ss[wmP + g + 8][kk + t]);
            a[2] = f2tf32(Ss[wmP + g    ][kk + t + 4]);
            a[3] = f2tf32(Ss[wmP + g + 8][kk + t + 4]);
            #pragma unroll
            for (int ni = 0; ni < 4; ni++) {
                uint32_t bb[2];
                int n = wnP + ni * 8 + g;
                bb[0] = KVs[kk + t    ][n];
                bb[1] = KVs[kk + t + 4][n];
                mma_tf32(O[ni], a, bb);
            }
        }
        __syncthreads();
    }

    // epilogue: divide by l, write tf32 bits (plain layout) for the Wo GEMM
    {
        float inv0 = 1.f / l_s[wmP + g];
        float inv1 = 1.f / l_s[wmP + g + 8];
        const size_t r0 = (size_t)(b*TT + q0 + wmP + g) * DD;
        const size_t r1 = (size_t)(b*TT + q0 + wmP + g + 8) * DD;
        #pragma unroll
        for (int ni = 0; ni < 4; ni++) {
            int col = h*128 + wnP + ni*8 + 2*t;
            *(uint2*)(g_attnout32 + r0 + col) =
                make_uint2(f2tf32(O[ni][0]*inv0), f2tf32(O[ni][1]*inv0));
            *(uint2*)(g_attnout32 + r1 + col) =
                make_uint2(f2tf32(O[ni][2]*inv1), f2tf32(O[ni][3]*inv1));
        }
    }
}

// ---------------------------------------------------------------------------
extern "C" void kernel_launch(void* const* d_in, const int* in_sizes, int n_in,
                              void* d_out, int out_size) {
    const float* x   = (const float*)d_in[0];
    const float* xs  = (const float*)d_in[1];
    const int*   vl  = (const int*)  d_in[2];
    const float* Wq  = (const float*)d_in[3];
    const float* Wk  = (const float*)d_in[4];
    const float* Wv  = (const float*)d_in[5];
    const float* Wo  = (const float*)d_in[6];
    const float* Wqs = (const float*)d_in[7];
    const float* Wks = (const float*)d_in[8];
    const float* Wvs = (const float*)d_in[9];
    const float* Wos = (const float*)d_in[10];
    const float* Wt  = (const float*)d_in[11];
    float* out = (float*)d_out;

    prep_w_kernel<<<dim3(4096, 4), 256>>>(Wq, Wk, Wv, Wo);
    woswt_kernel<<<256, 256>>>(Wos, Wt);
    spectral_kernel<<<MM, 256>>>(xs, Wqs, Wks, Wvs);
    xt_kernel<<<MM/16, 256>>>(x);
    qkv_gemm_kernel<<<dim3(24, 16), 256>>>();
    temporal_attn_kernel<<<dim3(TT/32, HH, BB), 256>>>(vl);
    out_gemm_kernel<<<dim3(8, 16), 256>>>(out);
}